// round 11
// baseline (speedup 1.0000x reference)
#include <cuda_runtime.h>
#include <cuda_fp16.h>
#include <math.h>
#include <stdint.h>

#define BB 4
#define TT 4096
#define CC 1024
#define HH 64

// Scratch for projected q,k,v (12 MB, __device__ globals per harness rules)
__device__ float g_q[(size_t)BB * TT * HH];
__device__ float g_k[(size_t)BB * TT * HH];
__device__ float g_v[(size_t)BB * TT * HH];

// ---------------------------------------------------------------------------
// helpers
// ---------------------------------------------------------------------------
__device__ __forceinline__ uint32_t f2tf(float f) {
    uint32_t u;
    asm("cvt.rna.tf32.f32 %0, %1;" : "=r"(u) : "f"(f));
    return u;
}
__device__ __forceinline__ uint4 f2tf4(float4 v) {
    uint4 u;
    u.x = f2tf(v.x); u.y = f2tf(v.y); u.z = f2tf(v.z); u.w = f2tf(v.w);
    return u;
}
__device__ __forceinline__ uint32_t packh2(float lo, float hi) {
    half2 h = __floats2half2_rn(lo, hi);
    return *(uint32_t*)&h;
}
__device__ __forceinline__ uint2 f4toh2x2(float4 v) {
    uint2 r;
    r.x = packh2(v.x, v.y);
    r.y = packh2(v.z, v.w);
    return r;
}

// tf32: D(16x8) += A(16x8) * B(8x8)
__device__ __forceinline__ void mma8(float* c,
                                     uint32_t a0, uint32_t a1, uint32_t a2, uint32_t a3,
                                     uint32_t b0, uint32_t b1) {
    asm volatile(
        "mma.sync.aligned.m16n8k8.row.col.f32.tf32.tf32.f32 "
        "{%0,%1,%2,%3}, {%4,%5,%6,%7}, {%8,%9}, {%0,%1,%2,%3};"
        : "+f"(c[0]), "+f"(c[1]), "+f"(c[2]), "+f"(c[3])
        : "r"(a0), "r"(a1), "r"(a2), "r"(a3), "r"(b0), "r"(b1));
}

// fp16: D(16x8, f32) += A(16x16, f16) * B(16x8, f16)
__device__ __forceinline__ void mma16(float* c,
                                      uint32_t a0, uint32_t a1, uint32_t a2, uint32_t a3,
                                      uint32_t b0, uint32_t b1) {
    asm volatile(
        "mma.sync.aligned.m16n8k16.row.col.f32.f16.f16.f32 "
        "{%0,%1,%2,%3}, {%4,%5,%6,%7}, {%8,%9}, {%0,%1,%2,%3};"
        : "+f"(c[0]), "+f"(c[1]), "+f"(c[2]), "+f"(c[3])
        : "r"(a0), "r"(a1), "r"(a2), "r"(a3), "r"(b0), "r"(b1));
}

// ---------------------------------------------------------------------------
// Kernel 1: fused QKV projection, tf32 mma, k-chunk software pipeline.
// (unchanged from round 6/8 — ~21 us)
// ---------------------------------------------------------------------------
#define PM  128
#define PKC 32
#define XP  36
#define WP  72
#define NKC (CC / PKC)

__global__ __launch_bounds__(256) void proj_kernel(
    const float* __restrict__ x,
    const float* __restrict__ Wk,
    const float* __restrict__ Wq,
    const float* __restrict__ Wv)
{
    __shared__ uint32_t Xs[PM * XP];
    __shared__ uint32_t Ws[3][PKC * WP];

    const int tid  = threadIdx.x;
    const int lane = tid & 31;
    const int wid  = tid >> 5;
    const int wm   = wid & 3;
    const int wn   = wid >> 2;
    const int g    = lane >> 2;
    const int t    = lane & 3;
    const int row0 = blockIdx.x * PM;
    const float* W[3] = {Wk, Wq, Wv};

    int xi[4], xc[4];
#pragma unroll
    for (int s = 0; s < 4; s++) {
        int idx = tid + s * 256;
        xi[s] = idx >> 3;
        xc[s] = (idx & 7) * 4;
    }
    int wr[2], wh[2];
#pragma unroll
    for (int s = 0; s < 2; s++) {
        int idx = tid + s * 256;
        wr[s] = idx >> 4;
        wh[s] = (idx & 15) * 4;
    }

    float acc[3][2][4][4];
#pragma unroll
    for (int m = 0; m < 3; m++)
#pragma unroll
        for (int mt = 0; mt < 2; mt++)
#pragma unroll
            for (int nt = 0; nt < 4; nt++)
#pragma unroll
                for (int e = 0; e < 4; e++) acc[m][mt][nt][e] = 0.f;

    float4 xbuf[4], wbuf[3][2];

#pragma unroll
    for (int s = 0; s < 4; s++)
        xbuf[s] = *(const float4*)(x + (size_t)(row0 + xi[s]) * CC + xc[s]);
#pragma unroll
    for (int s = 0; s < 2; s++)
#pragma unroll
        for (int m = 0; m < 3; m++)
            wbuf[m][s] = *(const float4*)(W[m] + (size_t)wr[s] * HH + wh[s]);
#pragma unroll
    for (int s = 0; s < 4; s++)
        *(uint4*)&Xs[xi[s] * XP + xc[s]] = f2tf4(xbuf[s]);
#pragma unroll
    for (int s = 0; s < 2; s++)
#pragma unroll
        for (int m = 0; m < 3; m++)
            *(uint4*)&Ws[m][wr[s] * WP + wh[s]] = f2tf4(wbuf[m][s]);
    __syncthreads();

    for (int kc = 0; kc < NKC; kc++) {
        const bool pf = (kc + 1) < NKC;
        if (pf) {
            const int kn = (kc + 1) * PKC;
#pragma unroll
            for (int s = 0; s < 4; s++)
                xbuf[s] = *(const float4*)(x + (size_t)(row0 + xi[s]) * CC + kn + xc[s]);
#pragma unroll
            for (int s = 0; s < 2; s++)
#pragma unroll
                for (int m = 0; m < 3; m++)
                    wbuf[m][s] = *(const float4*)(W[m] + (size_t)(kn + wr[s]) * HH + wh[s]);
        }

#pragma unroll
        for (int ks = 0; ks < 4; ks++) {
            const int k0 = ks * 8;
            uint32_t a[2][4];
#pragma unroll
            for (int mt = 0; mt < 2; mt++) {
                int ar = wm * 32 + mt * 16 + g;
                a[mt][0] = Xs[ar * XP + k0 + t];
                a[mt][1] = Xs[(ar + 8) * XP + k0 + t];
                a[mt][2] = Xs[ar * XP + k0 + t + 4];
                a[mt][3] = Xs[(ar + 8) * XP + k0 + t + 4];
            }
#pragma unroll
            for (int m = 0; m < 3; m++)
#pragma unroll
                for (int nt = 0; nt < 4; nt++) {
                    int n0 = wn * 32 + nt * 8;
                    uint32_t b0 = Ws[m][(k0 + t) * WP + n0 + g];
                    uint32_t b1 = Ws[m][(k0 + t + 4) * WP + n0 + g];
                    mma8(acc[m][0][nt], a[0][0], a[0][1], a[0][2], a[0][3], b0, b1);
                    mma8(acc[m][1][nt], a[1][0], a[1][1], a[1][2], a[1][3], b0, b1);
                }
        }

        if (pf) {
            __syncthreads();
#pragma unroll
            for (int s = 0; s < 4; s++)
                *(uint4*)&Xs[xi[s] * XP + xc[s]] = f2tf4(xbuf[s]);
#pragma unroll
            for (int s = 0; s < 2; s++)
#pragma unroll
                for (int m = 0; m < 3; m++)
                    *(uint4*)&Ws[m][wr[s] * WP + wh[s]] = f2tf4(wbuf[m][s]);
            __syncthreads();
        }
    }

    float* G[3] = {g_k, g_q, g_v};
#pragma unroll
    for (int m = 0; m < 3; m++)
#pragma unroll
        for (int mt = 0; mt < 2; mt++) {
            int r0 = row0 + wm * 32 + mt * 16 + g;
#pragma unroll
            for (int nt = 0; nt < 4; nt++) {
                int c0 = wn * 32 + nt * 8 + 2 * t;
                float* dst = G[m] + (size_t)r0 * HH + c0;
                *(float2*)dst = make_float2(acc[m][mt][nt][0], acc[m][mt][nt][1]);
                *(float2*)(dst + (size_t)8 * HH) =
                    make_float2(acc[m][mt][nt][2], acc[m][mt][nt][3]);
            }
        }
}

// ---------------------------------------------------------------------------
// Kernel 2: causal flash attention, fp16 m16n8k16 mma, P in registers.
// Block: 128 thr = 4 warps, one 64-row q-tile. Grid: 256 blocks, longest-
// first (qt = 63 - bid/4) so the qt=63 critical-path blocks start in wave 1.
// Double-buffered K/V (fp16, V transposed), ONE __syncthreads per KV tile.
// Smem 45 KB/block -> >=2 blocks co-resident per SM for latency hiding.
// Layouts (pitch 36 half2): Qh[row][h-pair], K[token][h-pair],
// Vt[h][token-pair] (element = {V[2j][h], V[2j+1][h]}).
// ---------------------------------------------------------------------------
#define AP 36    // pitch in half2 (u32) units; 36 % 32 == 4 -> conflict-free frags

__global__ __launch_bounds__(128, 2) void attn_kernel(float* __restrict__ out)
{
    __shared__ uint32_t Qh[64 * AP];
    __shared__ uint32_t Kb[2][64 * AP];
    __shared__ uint32_t Vb[2][64 * AP];

    const int tid  = threadIdx.x;
    const int lane = tid & 31;
    const int lw   = tid >> 5;              // warp 0..3 -> m16 slice
    const int g    = lane >> 2;
    const int t    = lane & 3;

    const int bid = blockIdx.x;             // 0..255
    const int qt  = 63 - (bid >> 2);        // longest first
    const int b   = bid & 3;
    const int qrow0 = qt * 64;
    const float scale = 0.03125f;           // 1024^-0.5

    // Per-thread load slots: 8 float4 per 64x64 tile
    int li[8], lh[8];
#pragma unroll
    for (int s = 0; s < 8; s++) {
        int idx = tid + s * 128;
        li[s] = idx >> 4;
        lh[s] = (idx & 15) * 4;
    }

    // Stage Q (scaled -> fp16) and tile 0 K/V
#pragma unroll
    for (int s = 0; s < 8; s++) {
        float4 qv = *(const float4*)(g_q + ((size_t)b * TT + qrow0 + li[s]) * HH + lh[s]);
        qv.x *= scale; qv.y *= scale; qv.z *= scale; qv.w *= scale;
        *(uint2*)&Qh[li[s] * AP + lh[s] / 2] = f4toh2x2(qv);
    }
    {
        half* vh = (half*)Vb[0];
#pragma unroll
        for (int s = 0; s < 8; s++) {
            size_t go = ((size_t)b * TT + li[s]) * HH + lh[s];
            *(uint2*)&Kb[0][li[s] * AP + lh[s] / 2] = f4toh2x2(*(const float4*)(g_k + go));
            float4 vv = *(const float4*)(g_v + go);
            int iw = li[s] >> 1, ib = li[s] & 1;
            vh[((lh[s] + 0) * AP + iw) * 2 + ib] = __float2half_rn(vv.x);
            vh[((lh[s] + 1) * AP + iw) * 2 + ib] = __float2half_rn(vv.y);
            vh[((lh[s] + 2) * AP + iw) * 2 + ib] = __float2half_rn(vv.z);
            vh[((lh[s] + 3) * AP + iw) * 2 + ib] = __float2half_rn(vv.w);
        }
    }
    __syncthreads();

    float m0v = -INFINITY, m1v = -INFINITY, l0 = 0.f, l1 = 0.f;
    float O[8][4];
#pragma unroll
    for (int nt = 0; nt < 8; nt++)
#pragma unroll
        for (int e = 0; e < 4; e++) O[nt][e] = 0.f;

    const int arow = lw * 16 + g;
    int pb = 0;

    for (int kt = 0; kt <= qt; kt++) {
        const uint32_t* Kc = Kb[pb];
        const uint32_t* Vc = Vb[pb];
        uint32_t* Kn = Kb[1 - pb];
        half*     Vn = (half*)Vb[1 - pb];

        // Prefetch next K/V tile into registers
        const bool pf = kt < qt;
        float4 kbuf[8], vbuf[8];
        if (pf) {
            const size_t rb = (size_t)b * TT + (size_t)(kt + 1) * 64;
#pragma unroll
            for (int s = 0; s < 8; s++) {
                size_t go = (rb + li[s]) * HH + lh[s];
                kbuf[s] = *(const float4*)(g_k + go);
                vbuf[s] = *(const float4*)(g_v + go);
            }
        }

        // S = Qh * Kc^T  (fp16 m16n8k16: 4 k-chunks x 8 n-tiles)
        float S[8][4];
#pragma unroll
        for (int nt = 0; nt < 8; nt++)
#pragma unroll
            for (int e = 0; e < 4; e++) S[nt][e] = 0.f;

#pragma unroll
        for (int kc = 0; kc < 4; kc++) {
            const int k0 = kc * 8;
            uint32_t a0 = Qh[arow * AP + k0 + t];
            uint32_t a1 = Qh[(arow + 8) * AP + k0 + t];
            uint32_t a2 = Qh[arow * AP + k0 + t + 4];
            uint32_t a3 = Qh[(arow + 8) * AP + k0 + t + 4];
#pragma unroll
            for (int nt = 0; nt < 8; nt++) {
                uint32_t b0 = Kc[(nt * 8 + g) * AP + k0 + t];
                uint32_t b1 = Kc[(nt * 8 + g) * AP + k0 + t + 4];
                mma16(S[nt], a0, a1, a2, a3, b0, b1);
            }
        }

        // Causal mask (diagonal tile only)
        if (kt == qt) {
            const int krow0 = kt * 64;
            int r0 = qrow0 + arow, r1 = r0 + 8;
#pragma unroll
            for (int nt = 0; nt < 8; nt++) {
                int c = krow0 + nt * 8 + 2 * t;
                if (c     > r0) S[nt][0] = -INFINITY;
                if (c + 1 > r0) S[nt][1] = -INFINITY;
                if (c     > r1) S[nt][2] = -INFINITY;
                if (c + 1 > r1) S[nt][3] = -INFINITY;
            }
        }

        // Row max over lane quad
        float mt0 = -INFINITY, mt1 = -INFINITY;
#pragma unroll
        for (int nt = 0; nt < 8; nt++) {
            mt0 = fmaxf(mt0, fmaxf(S[nt][0], S[nt][1]));
            mt1 = fmaxf(mt1, fmaxf(S[nt][2], S[nt][3]));
        }
        mt0 = fmaxf(mt0, __shfl_xor_sync(0xffffffffu, mt0, 1));
        mt0 = fmaxf(mt0, __shfl_xor_sync(0xffffffffu, mt0, 2));
        mt1 = fmaxf(mt1, __shfl_xor_sync(0xffffffffu, mt1, 1));
        mt1 = fmaxf(mt1, __shfl_xor_sync(0xffffffffu, mt1, 2));

        float mn0 = fmaxf(m0v, mt0), mn1 = fmaxf(m1v, mt1);
        float cr0 = __expf(m0v - mn0), cr1 = __expf(m1v - mn1);

        // P = exp(S - mn): pack straight into fp16 A-fragments (no smem!)
        uint32_t pl[8], ph[8];
        float rs0 = 0.f, rs1 = 0.f;
#pragma unroll
        for (int nt = 0; nt < 8; nt++) {
            float p0 = __expf(S[nt][0] - mn0);
            float p1 = __expf(S[nt][1] - mn0);
            float p2 = __expf(S[nt][2] - mn1);
            float p3 = __expf(S[nt][3] - mn1);
            rs0 += p0 + p1;
            rs1 += p2 + p3;
            pl[nt] = packh2(p0, p1);
            ph[nt] = packh2(p2, p3);
        }
        rs0 += __shfl_xor_sync(0xffffffffu, rs0, 1);
        rs0 += __shfl_xor_sync(0xffffffffu, rs0, 2);
        rs1 += __shfl_xor_sync(0xffffffffu, rs1, 1);
        rs1 += __shfl_xor_sync(0xffffffffu, rs1, 2);

        l0 = l0 * cr0 + rs0;
        l1 = l1 * cr1 + rs1;
        m0v = mn0; m1v = mn1;
#pragma unroll
        for (int nt = 0; nt < 8; nt++) {
            O[nt][0] *= cr0; O[nt][1] *= cr0;
            O[nt][2] *= cr1; O[nt][3] *= cr1;
        }

        // Stage prefetched tile into alternate buffers (overlaps PV issue)
        if (pf) {
#pragma unroll
            for (int s = 0; s < 8; s++) {
                *(uint2*)&Kn[li[s] * AP + lh[s] / 2] = f4toh2x2(kbuf[s]);
                int iw = li[s] >> 1, ib = li[s] & 1;
                Vn[((lh[s] + 0) * AP + iw) * 2 + ib] = __float2half_rn(vbuf[s].x);
                Vn[((lh[s] + 1) * AP + iw) * 2 + ib] = __float2half_rn(vbuf[s].y);
                Vn[((lh[s] + 2) * AP + iw) * 2 + ib] = __float2half_rn(vbuf[s].z);
                Vn[((lh[s] + 3) * AP + iw) * 2 + ib] = __float2half_rn(vbuf[s].w);
            }
        }

        // O += P * V   (A = P from registers, B = Vt from smem)
#pragma unroll
        for (int kc = 0; kc < 4; kc++) {
            uint32_t a0 = pl[2 * kc], a1 = ph[2 * kc];
            uint32_t a2 = pl[2 * kc + 1], a3 = ph[2 * kc + 1];
            const int k0 = kc * 8;
#pragma unroll
            for (int nt = 0; nt < 8; nt++) {
                uint32_t b0 = Vc[(nt * 8 + g) * AP + k0 + t];
                uint32_t b1 = Vc[(nt * 8 + g) * AP + k0 + t + 4];
                mma16(O[nt], a0, a1, a2, a3, b0, b1);
            }
        }
        __syncthreads();   // staging visible + current buffers fully consumed
        pb ^= 1;
    }

    // Normalize and write
    float i0 = 1.0f / l0, i1 = 1.0f / l1;
    const int r0 = qrow0 + arow;
#pragma unroll
    for (int nt = 0; nt < 8; nt++) {
        size_t o0 = ((size_t)b * TT + r0) * HH + nt * 8 + 2 * t;
        *(float2*)(out + o0)                  = make_float2(O[nt][0] * i0, O[nt][1] * i0);
        *(float2*)(out + o0 + (size_t)8 * HH) = make_float2(O[nt][2] * i1, O[nt][3] * i1);
    }
}

// ---------------------------------------------------------------------------
extern "C" void kernel_launch(void* const* d_in, const int* in_sizes, int n_in,
                              void* d_out, int out_size)
{
    const float* x  = (const float*)d_in[0];
    const float* Wk = (const float*)d_in[1];
    const float* Wq = (const float*)d_in[2];
    const float* Wv = (const float*)d_in[3];
    float* out = (float*)d_out;

    proj_kernel<<<(BB * TT) / PM, 256>>>(x, Wk, Wq, Wv);
    attn_kernel<<<256, 128>>>(out);
}

// round 13
// speedup vs baseline: 1.1996x; 1.1996x over previous
#include <cuda_runtime.h>
#include <cuda_fp16.h>
#include <math.h>
#include <stdint.h>

#define BB 4
#define TT 4096
#define CC 1024
#define HH 64

// Scratch for projected q,k,v (12 MB, __device__ globals per harness rules)
__device__ float g_q[(size_t)BB * TT * HH];
__device__ float g_k[(size_t)BB * TT * HH];
__device__ float g_v[(size_t)BB * TT * HH];

// ---------------------------------------------------------------------------
// helpers
// ---------------------------------------------------------------------------
__device__ __forceinline__ uint32_t f2tf(float f) {
    uint32_t u;
    asm("cvt.rna.tf32.f32 %0, %1;" : "=r"(u) : "f"(f));
    return u;
}
__device__ __forceinline__ uint4 f2tf4(float4 v) {
    uint4 u;
    u.x = f2tf(v.x); u.y = f2tf(v.y); u.z = f2tf(v.z); u.w = f2tf(v.w);
    return u;
}
__device__ __forceinline__ uint32_t packh2(float lo, float hi) {
    half2 h = __floats2half2_rn(lo, hi);
    return *(uint32_t*)&h;
}
__device__ __forceinline__ uint2 f4toh2x2(float4 v) {
    uint2 r;
    r.x = packh2(v.x, v.y);
    r.y = packh2(v.z, v.w);
    return r;
}

// tf32: D(16x8) += A(16x8) * B(8x8)
__device__ __forceinline__ void mma8(float* c,
                                     uint32_t a0, uint32_t a1, uint32_t a2, uint32_t a3,
                                     uint32_t b0, uint32_t b1) {
    asm volatile(
        "mma.sync.aligned.m16n8k8.row.col.f32.tf32.tf32.f32 "
        "{%0,%1,%2,%3}, {%4,%5,%6,%7}, {%8,%9}, {%0,%1,%2,%3};"
        : "+f"(c[0]), "+f"(c[1]), "+f"(c[2]), "+f"(c[3])
        : "r"(a0), "r"(a1), "r"(a2), "r"(a3), "r"(b0), "r"(b1));
}

// fp16: D(16x8, f32) += A(16x16, f16) * B(16x8, f16)
__device__ __forceinline__ void mma16(float* c,
                                      uint32_t a0, uint32_t a1, uint32_t a2, uint32_t a3,
                                      uint32_t b0, uint32_t b1) {
    asm volatile(
        "mma.sync.aligned.m16n8k16.row.col.f32.f16.f16.f32 "
        "{%0,%1,%2,%3}, {%4,%5,%6,%7}, {%8,%9}, {%0,%1,%2,%3};"
        : "+f"(c[0]), "+f"(c[1]), "+f"(c[2]), "+f"(c[3])
        : "r"(a0), "r"(a1), "r"(a2), "r"(a3), "r"(b0), "r"(b1));
}

// ---------------------------------------------------------------------------
// Kernel 1: fused QKV projection, tf32 mma, k-chunk software pipeline.
// (unchanged — reliably ~21 us)
// ---------------------------------------------------------------------------
#define PM  128
#define PKC 32
#define XP  36
#define WP  72
#define NKC (CC / PKC)

__global__ __launch_bounds__(256) void proj_kernel(
    const float* __restrict__ x,
    const float* __restrict__ Wk,
    const float* __restrict__ Wq,
    const float* __restrict__ Wv)
{
    __shared__ uint32_t Xs[PM * XP];
    __shared__ uint32_t Ws[3][PKC * WP];

    const int tid  = threadIdx.x;
    const int lane = tid & 31;
    const int wid  = tid >> 5;
    const int wm   = wid & 3;
    const int wn   = wid >> 2;
    const int g    = lane >> 2;
    const int t    = lane & 3;
    const int row0 = blockIdx.x * PM;
    const float* W[3] = {Wk, Wq, Wv};

    int xi[4], xc[4];
#pragma unroll
    for (int s = 0; s < 4; s++) {
        int idx = tid + s * 256;
        xi[s] = idx >> 3;
        xc[s] = (idx & 7) * 4;
    }
    int wr[2], wh[2];
#pragma unroll
    for (int s = 0; s < 2; s++) {
        int idx = tid + s * 256;
        wr[s] = idx >> 4;
        wh[s] = (idx & 15) * 4;
    }

    float acc[3][2][4][4];
#pragma unroll
    for (int m = 0; m < 3; m++)
#pragma unroll
        for (int mt = 0; mt < 2; mt++)
#pragma unroll
            for (int nt = 0; nt < 4; nt++)
#pragma unroll
                for (int e = 0; e < 4; e++) acc[m][mt][nt][e] = 0.f;

    float4 xbuf[4], wbuf[3][2];

#pragma unroll
    for (int s = 0; s < 4; s++)
        xbuf[s] = *(const float4*)(x + (size_t)(row0 + xi[s]) * CC + xc[s]);
#pragma unroll
    for (int s = 0; s < 2; s++)
#pragma unroll
        for (int m = 0; m < 3; m++)
            wbuf[m][s] = *(const float4*)(W[m] + (size_t)wr[s] * HH + wh[s]);
#pragma unroll
    for (int s = 0; s < 4; s++)
        *(uint4*)&Xs[xi[s] * XP + xc[s]] = f2tf4(xbuf[s]);
#pragma unroll
    for (int s = 0; s < 2; s++)
#pragma unroll
        for (int m = 0; m < 3; m++)
            *(uint4*)&Ws[m][wr[s] * WP + wh[s]] = f2tf4(wbuf[m][s]);
    __syncthreads();

    for (int kc = 0; kc < NKC; kc++) {
        const bool pf = (kc + 1) < NKC;
        if (pf) {
            const int kn = (kc + 1) * PKC;
#pragma unroll
            for (int s = 0; s < 4; s++)
                xbuf[s] = *(const float4*)(x + (size_t)(row0 + xi[s]) * CC + kn + xc[s]);
#pragma unroll
            for (int s = 0; s < 2; s++)
#pragma unroll
                for (int m = 0; m < 3; m++)
                    wbuf[m][s] = *(const float4*)(W[m] + (size_t)(kn + wr[s]) * HH + wh[s]);
        }

#pragma unroll
        for (int ks = 0; ks < 4; ks++) {
            const int k0 = ks * 8;
            uint32_t a[2][4];
#pragma unroll
            for (int mt = 0; mt < 2; mt++) {
                int ar = wm * 32 + mt * 16 + g;
                a[mt][0] = Xs[ar * XP + k0 + t];
                a[mt][1] = Xs[(ar + 8) * XP + k0 + t];
                a[mt][2] = Xs[ar * XP + k0 + t + 4];
                a[mt][3] = Xs[(ar + 8) * XP + k0 + t + 4];
            }
#pragma unroll
            for (int m = 0; m < 3; m++)
#pragma unroll
                for (int nt = 0; nt < 4; nt++) {
                    int n0 = wn * 32 + nt * 8;
                    uint32_t b0 = Ws[m][(k0 + t) * WP + n0 + g];
                    uint32_t b1 = Ws[m][(k0 + t + 4) * WP + n0 + g];
                    mma8(acc[m][0][nt], a[0][0], a[0][1], a[0][2], a[0][3], b0, b1);
                    mma8(acc[m][1][nt], a[1][0], a[1][1], a[1][2], a[1][3], b0, b1);
                }
        }

        if (pf) {
            __syncthreads();
#pragma unroll
            for (int s = 0; s < 4; s++)
                *(uint4*)&Xs[xi[s] * XP + xc[s]] = f2tf4(xbuf[s]);
#pragma unroll
            for (int s = 0; s < 2; s++)
#pragma unroll
                for (int m = 0; m < 3; m++)
                    *(uint4*)&Ws[m][wr[s] * WP + wh[s]] = f2tf4(wbuf[m][s]);
            __syncthreads();
        }
    }

    float* G[3] = {g_k, g_q, g_v};
#pragma unroll
    for (int m = 0; m < 3; m++)
#pragma unroll
        for (int mt = 0; mt < 2; mt++) {
            int r0 = row0 + wm * 32 + mt * 16 + g;
#pragma unroll
            for (int nt = 0; nt < 4; nt++) {
                int c0 = wn * 32 + nt * 8 + 2 * t;
                float* dst = G[m] + (size_t)r0 * HH + c0;
                *(float2*)dst = make_float2(acc[m][mt][nt][0], acc[m][mt][nt][1]);
                *(float2*)(dst + (size_t)8 * HH) =
                    make_float2(acc[m][mt][nt][2], acc[m][mt][nt][3]);
            }
        }
}

// ---------------------------------------------------------------------------
// Kernel 2: causal flash attention, fp16 m16n8k16, P in registers,
// BALANCED PAIR schedule: 256 thr = 2 independent 128-thr groups; group grp
// handles q-tile (p / 63-p) => every block does exactly 65 KV tile-units.
// Grid 128 = one balanced wave. Double-buffered fp16 K/V (V transposed),
// ONE named barrier (128-thr scope) per KV tile.
// Layouts (pitch 36 u32=half2): Qh[row][hpair], K[token][hpair],
// Vt[h][tokenpair] (element = {V[2j][h], V[2j+1][h]}).
// ---------------------------------------------------------------------------
#define AP 36
#define GRP_U32 (5 * 64 * AP)                    // Qh + K0 + K1 + V0 + V1
#define ATTN_SMEM (2 * GRP_U32 * 4)              // 184320 B? no: 5*64*36=11520 u32 -> 46080 B * 2 = 92160 B

__device__ __forceinline__ void group_bar(int id) {
    asm volatile("bar.sync %0, %1;" :: "r"(id), "r"(128) : "memory");
}

__global__ __launch_bounds__(256, 1) void attn_kernel(float* __restrict__ out)
{
    extern __shared__ uint32_t sm[];
    const int tid  = threadIdx.x;
    const int lane = tid & 31;
    const int wid  = tid >> 5;
    const int grp  = wid >> 2;              // 0 or 1
    const int lw   = wid & 3;               // m16 slice within group
    const int gtid = tid & 127;
    const int g    = lane >> 2;
    const int t    = lane & 3;
    const int bar  = grp + 1;

    uint32_t* base = sm + grp * GRP_U32;
    uint32_t* Qh   = base;
    uint32_t* Kb0  = base + 1 * 64 * AP;
    uint32_t* Kb1  = base + 2 * 64 * AP;
    uint32_t* Vb0  = base + 3 * 64 * AP;
    uint32_t* Vb1  = base + 4 * 64 * AP;

    const int b  = blockIdx.y;
    const int p  = blockIdx.x;              // 0..31
    const int qt = grp ? (63 - p) : p;
    const int qrow0 = qt * 64;
    const float scale = 0.03125f;           // 1024^-0.5

    // Per-thread load slots: 8 float4 per 64x64 tile (128 threads)
    int li[8], lh[8];
#pragma unroll
    for (int s = 0; s < 8; s++) {
        int idx = gtid + s * 128;
        li[s] = idx >> 4;
        lh[s] = (idx & 15) * 4;
    }

    // Stage Q (scaled -> fp16) and tile 0 K/V
#pragma unroll
    for (int s = 0; s < 8; s++) {
        float4 qv = *(const float4*)(g_q + ((size_t)b * TT + qrow0 + li[s]) * HH + lh[s]);
        qv.x *= scale; qv.y *= scale; qv.z *= scale; qv.w *= scale;
        *(uint2*)&Qh[li[s] * AP + lh[s] / 2] = f4toh2x2(qv);
    }
    {
        half* vh = (half*)Vb0;
#pragma unroll
        for (int s = 0; s < 8; s++) {
            size_t go = ((size_t)b * TT + li[s]) * HH + lh[s];
            *(uint2*)&Kb0[li[s] * AP + lh[s] / 2] = f4toh2x2(*(const float4*)(g_k + go));
            float4 vv = *(const float4*)(g_v + go);
            int iw = li[s] >> 1, ib = li[s] & 1;
            vh[((lh[s] + 0) * AP + iw) * 2 + ib] = __float2half_rn(vv.x);
            vh[((lh[s] + 1) * AP + iw) * 2 + ib] = __float2half_rn(vv.y);
            vh[((lh[s] + 2) * AP + iw) * 2 + ib] = __float2half_rn(vv.z);
            vh[((lh[s] + 3) * AP + iw) * 2 + ib] = __float2half_rn(vv.w);
        }
    }
    group_bar(bar);

    float m0v = -INFINITY, m1v = -INFINITY, l0 = 0.f, l1 = 0.f;
    float O[8][4];
#pragma unroll
    for (int nt = 0; nt < 8; nt++)
#pragma unroll
        for (int e = 0; e < 4; e++) O[nt][e] = 0.f;

    const int arow = lw * 16 + g;
    int pb = 0;

    for (int kt = 0; kt <= qt; kt++) {
        const uint32_t* Kc = pb ? Kb1 : Kb0;
        const uint32_t* Vc = pb ? Vb1 : Vb0;
        uint32_t* Kn = pb ? Kb0 : Kb1;
        half*     Vn = (half*)(pb ? Vb0 : Vb1);

        // Prefetch next K/V tile into registers
        const bool pf = kt < qt;
        float4 kbuf[8], vbuf[8];
        if (pf) {
            const size_t rb = (size_t)b * TT + (size_t)(kt + 1) * 64;
#pragma unroll
            for (int s = 0; s < 8; s++) {
                size_t go = (rb + li[s]) * HH + lh[s];
                kbuf[s] = *(const float4*)(g_k + go);
                vbuf[s] = *(const float4*)(g_v + go);
            }
        }

        // S = Qh * Kc^T  (fp16 m16n8k16: 4 k-chunks x 8 n-tiles)
        float S[8][4];
#pragma unroll
        for (int nt = 0; nt < 8; nt++)
#pragma unroll
            for (int e = 0; e < 4; e++) S[nt][e] = 0.f;

#pragma unroll
        for (int kc = 0; kc < 4; kc++) {
            const int k0 = kc * 8;
            uint32_t a0 = Qh[arow * AP + k0 + t];
            uint32_t a1 = Qh[(arow + 8) * AP + k0 + t];
            uint32_t a2 = Qh[arow * AP + k0 + t + 4];
            uint32_t a3 = Qh[(arow + 8) * AP + k0 + t + 4];
#pragma unroll
            for (int nt = 0; nt < 8; nt++) {
                uint32_t b0 = Kc[(nt * 8 + g) * AP + k0 + t];
                uint32_t b1 = Kc[(nt * 8 + g) * AP + k0 + t + 4];
                mma16(S[nt], a0, a1, a2, a3, b0, b1);
            }
        }

        // Causal mask (diagonal tile only)
        if (kt == qt) {
            const int krow0 = kt * 64;
            int r0 = qrow0 + arow, r1 = r0 + 8;
#pragma unroll
            for (int nt = 0; nt < 8; nt++) {
                int c = krow0 + nt * 8 + 2 * t;
                if (c     > r0) S[nt][0] = -INFINITY;
                if (c + 1 > r0) S[nt][1] = -INFINITY;
                if (c     > r1) S[nt][2] = -INFINITY;
                if (c + 1 > r1) S[nt][3] = -INFINITY;
            }
        }

        // Row max over lane quad
        float mt0 = -INFINITY, mt1 = -INFINITY;
#pragma unroll
        for (int nt = 0; nt < 8; nt++) {
            mt0 = fmaxf(mt0, fmaxf(S[nt][0], S[nt][1]));
            mt1 = fmaxf(mt1, fmaxf(S[nt][2], S[nt][3]));
        }
        mt0 = fmaxf(mt0, __shfl_xor_sync(0xffffffffu, mt0, 1));
        mt0 = fmaxf(mt0, __shfl_xor_sync(0xffffffffu, mt0, 2));
        mt1 = fmaxf(mt1, __shfl_xor_sync(0xffffffffu, mt1, 1));
        mt1 = fmaxf(mt1, __shfl_xor_sync(0xffffffffu, mt1, 2));

        float mn0 = fmaxf(m0v, mt0), mn1 = fmaxf(m1v, mt1);
        float cr0 = __expf(m0v - mn0), cr1 = __expf(m1v - mn1);

        // P = exp(S - mn): pack straight into fp16 A-fragments (no smem)
        uint32_t pl[8], ph[8];
        float rs0 = 0.f, rs1 = 0.f;
#pragma unroll
        for (int nt = 0; nt < 8; nt++) {
            float p0 = __expf(S[nt][0] - mn0);
            float p1 = __expf(S[nt][1] - mn0);
            float p2 = __expf(S[nt][2] - mn1);
            float p3 = __expf(S[nt][3] - mn1);
            rs0 += p0 + p1;
            rs1 += p2 + p3;
            pl[nt] = packh2(p0, p1);
            ph[nt] = packh2(p2, p3);
        }
        rs0 += __shfl_xor_sync(0xffffffffu, rs0, 1);
        rs0 += __shfl_xor_sync(0xffffffffu, rs0, 2);
        rs1 += __shfl_xor_sync(0xffffffffu, rs1, 1);
        rs1 += __shfl_xor_sync(0xffffffffu, rs1, 2);

        l0 = l0 * cr0 + rs0;
        l1 = l1 * cr1 + rs1;
        m0v = mn0; m1v = mn1;
#pragma unroll
        for (int nt = 0; nt < 8; nt++) {
            O[nt][0] *= cr0; O[nt][1] *= cr0;
            O[nt][2] *= cr1; O[nt][3] *= cr1;
        }

        // Stage prefetched tile into alternate buffers (overlaps PV issue)
        if (pf) {
#pragma unroll
            for (int s = 0; s < 8; s++) {
                *(uint2*)&Kn[li[s] * AP + lh[s] / 2] = f4toh2x2(kbuf[s]);
                int iw = li[s] >> 1, ib = li[s] & 1;
                Vn[((lh[s] + 0) * AP + iw) * 2 + ib] = __float2half_rn(vbuf[s].x);
                Vn[((lh[s] + 1) * AP + iw) * 2 + ib] = __float2half_rn(vbuf[s].y);
                Vn[((lh[s] + 2) * AP + iw) * 2 + ib] = __float2half_rn(vbuf[s].z);
                Vn[((lh[s] + 3) * AP + iw) * 2 + ib] = __float2half_rn(vbuf[s].w);
            }
        }

        // O += P * V   (A = P from registers, B = Vt from smem)
#pragma unroll
        for (int kc = 0; kc < 4; kc++) {
            uint32_t a0 = pl[2 * kc], a1 = ph[2 * kc];
            uint32_t a2 = pl[2 * kc + 1], a3 = ph[2 * kc + 1];
            const int k0 = kc * 8;
#pragma unroll
            for (int nt = 0; nt < 8; nt++) {
                uint32_t b0 = Vc[(nt * 8 + g) * AP + k0 + t];
                uint32_t b1 = Vc[(nt * 8 + g) * AP + k0 + t + 4];
                mma16(O[nt], a0, a1, a2, a3, b0, b1);
            }
        }
        group_bar(bar);   // staging visible + current buffers fully consumed
        pb ^= 1;
    }

    // Normalize and write
    float i0 = 1.0f / l0, i1 = 1.0f / l1;
    const int r0 = qrow0 + arow;
#pragma unroll
    for (int nt = 0; nt < 8; nt++) {
        size_t o0 = ((size_t)b * TT + r0) * HH + nt * 8 + 2 * t;
        *(float2*)(out + o0)                  = make_float2(O[nt][0] * i0, O[nt][1] * i0);
        *(float2*)(out + o0 + (size_t)8 * HH) = make_float2(O[nt][2] * i1, O[nt][3] * i1);
    }
}

// ---------------------------------------------------------------------------
extern "C" void kernel_launch(void* const* d_in, const int* in_sizes, int n_in,
                              void* d_out, int out_size)
{
    const float* x  = (const float*)d_in[0];
    const float* Wk = (const float*)d_in[1];
    const float* Wq = (const float*)d_in[2];
    const float* Wv = (const float*)d_in[3];
    float* out = (float*)d_out;

    proj_kernel<<<(BB * TT) / PM, 256>>>(x, Wk, Wq, Wv);

    cudaFuncSetAttribute(attn_kernel,
                         cudaFuncAttributeMaxDynamicSharedMemorySize,
                         ATTN_SMEM);
    attn_kernel<<<dim3(32, BB), 256, ATTN_SMEM>>>(out);
}

// round 17
// speedup vs baseline: 1.2047x; 1.0043x over previous
#include <cuda_runtime.h>
#include <cuda_fp16.h>
#include <math.h>
#include <stdint.h>

#define BB 4
#define TT 4096
#define CC 1024
#define HH 64

#define NQT   64            // q-tiles per batch (64 rows each)
#define CH    8             // KV tiles per chunk
#define MAXC  8             // max chunks per q-tile
#define NCHB  288           // sum over qt of ceil((qt+1)/8), per batch

// Scratch (device globals per harness rules)
__device__ float g_q[(size_t)BB * TT * HH];
__device__ float g_k[(size_t)BB * TT * HH];
__device__ float g_v[(size_t)BB * TT * HH];
// split-KV partials: O (unnormalized), m, l  per (b, qt, chunk)
__device__ float g_Opart[(size_t)BB * NQT * MAXC * 64 * 64];   // 33.5 MB
__device__ float g_mpart[(size_t)BB * NQT * MAXC * 64];
__device__ float g_lpart[(size_t)BB * NQT * MAXC * 64];

// ---------------------------------------------------------------------------
// helpers
// ---------------------------------------------------------------------------
__device__ __forceinline__ uint32_t f2tf(float f) {
    uint32_t u;
    asm("cvt.rna.tf32.f32 %0, %1;" : "=r"(u) : "f"(f));
    return u;
}
__device__ __forceinline__ uint4 f2tf4(float4 v) {
    uint4 u;
    u.x = f2tf(v.x); u.y = f2tf(v.y); u.z = f2tf(v.z); u.w = f2tf(v.w);
    return u;
}
__device__ __forceinline__ uint32_t packh2(float lo, float hi) {
    half2 h = __floats2half2_rn(lo, hi);
    return *(uint32_t*)&h;
}
__device__ __forceinline__ uint2 f4toh2x2(float4 v) {
    uint2 r;
    r.x = packh2(v.x, v.y);
    r.y = packh2(v.z, v.w);
    return r;
}

// tf32: D(16x8) += A(16x8) * B(8x8)
__device__ __forceinline__ void mma8(float* c,
                                     uint32_t a0, uint32_t a1, uint32_t a2, uint32_t a3,
                                     uint32_t b0, uint32_t b1) {
    asm volatile(
        "mma.sync.aligned.m16n8k8.row.col.f32.tf32.tf32.f32 "
        "{%0,%1,%2,%3}, {%4,%5,%6,%7}, {%8,%9}, {%0,%1,%2,%3};"
        : "+f"(c[0]), "+f"(c[1]), "+f"(c[2]), "+f"(c[3])
        : "r"(a0), "r"(a1), "r"(a2), "r"(a3), "r"(b0), "r"(b1));
}

// fp16: D(16x8, f32) += A(16x16, f16) * B(16x8, f16)
__device__ __forceinline__ void mma16(float* c,
                                      uint32_t a0, uint32_t a1, uint32_t a2, uint32_t a3,
                                      uint32_t b0, uint32_t b1) {
    asm volatile(
        "mma.sync.aligned.m16n8k16.row.col.f32.f16.f16.f32 "
        "{%0,%1,%2,%3}, {%4,%5,%6,%7}, {%8,%9}, {%0,%1,%2,%3};"
        : "+f"(c[0]), "+f"(c[1]), "+f"(c[2]), "+f"(c[3])
        : "r"(a0), "r"(a1), "r"(a2), "r"(a3), "r"(b0), "r"(b1));
}

// ---------------------------------------------------------------------------
// Kernel 1: fused QKV projection, tf32 mma, k-chunk software pipeline.
// (unchanged — ~21 us)
// ---------------------------------------------------------------------------
#define PM  128
#define PKC 32
#define XP  36
#define WP  72
#define NKC (CC / PKC)

__global__ __launch_bounds__(256) void proj_kernel(
    const float* __restrict__ x,
    const float* __restrict__ Wk,
    const float* __restrict__ Wq,
    const float* __restrict__ Wv)
{
    __shared__ uint32_t Xs[PM * XP];
    __shared__ uint32_t Ws[3][PKC * WP];

    const int tid  = threadIdx.x;
    const int lane = tid & 31;
    const int wid  = tid >> 5;
    const int wm   = wid & 3;
    const int wn   = wid >> 2;
    const int g    = lane >> 2;
    const int t    = lane & 3;
    const int row0 = blockIdx.x * PM;
    const float* W[3] = {Wk, Wq, Wv};

    int xi[4], xc[4];
#pragma unroll
    for (int s = 0; s < 4; s++) {
        int idx = tid + s * 256;
        xi[s] = idx >> 3;
        xc[s] = (idx & 7) * 4;
    }
    int wr[2], wh[2];
#pragma unroll
    for (int s = 0; s < 2; s++) {
        int idx = tid + s * 256;
        wr[s] = idx >> 4;
        wh[s] = (idx & 15) * 4;
    }

    float acc[3][2][4][4];
#pragma unroll
    for (int m = 0; m < 3; m++)
#pragma unroll
        for (int mt = 0; mt < 2; mt++)
#pragma unroll
            for (int nt = 0; nt < 4; nt++)
#pragma unroll
                for (int e = 0; e < 4; e++) acc[m][mt][nt][e] = 0.f;

    float4 xbuf[4], wbuf[3][2];

#pragma unroll
    for (int s = 0; s < 4; s++)
        xbuf[s] = *(const float4*)(x + (size_t)(row0 + xi[s]) * CC + xc[s]);
#pragma unroll
    for (int s = 0; s < 2; s++)
#pragma unroll
        for (int m = 0; m < 3; m++)
            wbuf[m][s] = *(const float4*)(W[m] + (size_t)wr[s] * HH + wh[s]);
#pragma unroll
    for (int s = 0; s < 4; s++)
        *(uint4*)&Xs[xi[s] * XP + xc[s]] = f2tf4(xbuf[s]);
#pragma unroll
    for (int s = 0; s < 2; s++)
#pragma unroll
        for (int m = 0; m < 3; m++)
            *(uint4*)&Ws[m][wr[s] * WP + wh[s]] = f2tf4(wbuf[m][s]);
    __syncthreads();

    for (int kc = 0; kc < NKC; kc++) {
        const bool pf = (kc + 1) < NKC;
        if (pf) {
            const int kn = (kc + 1) * PKC;
#pragma unroll
            for (int s = 0; s < 4; s++)
                xbuf[s] = *(const float4*)(x + (size_t)(row0 + xi[s]) * CC + kn + xc[s]);
#pragma unroll
            for (int s = 0; s < 2; s++)
#pragma unroll
                for (int m = 0; m < 3; m++)
                    wbuf[m][s] = *(const float4*)(W[m] + (size_t)(kn + wr[s]) * HH + wh[s]);
        }

#pragma unroll
        for (int ks = 0; ks < 4; ks++) {
            const int k0 = ks * 8;
            uint32_t a[2][4];
#pragma unroll
            for (int mt = 0; mt < 2; mt++) {
                int ar = wm * 32 + mt * 16 + g;
                a[mt][0] = Xs[ar * XP + k0 + t];
                a[mt][1] = Xs[(ar + 8) * XP + k0 + t];
                a[mt][2] = Xs[ar * XP + k0 + t + 4];
                a[mt][3] = Xs[(ar + 8) * XP + k0 + t + 4];
            }
#pragma unroll
            for (int m = 0; m < 3; m++)
#pragma unroll
                for (int nt = 0; nt < 4; nt++) {
                    int n0 = wn * 32 + nt * 8;
                    uint32_t b0 = Ws[m][(k0 + t) * WP + n0 + g];
                    uint32_t b1 = Ws[m][(k0 + t + 4) * WP + n0 + g];
                    mma8(acc[m][0][nt], a[0][0], a[0][1], a[0][2], a[0][3], b0, b1);
                    mma8(acc[m][1][nt], a[1][0], a[1][1], a[1][2], a[1][3], b0, b1);
                }
        }

        if (pf) {
            __syncthreads();
#pragma unroll
            for (int s = 0; s < 4; s++)
                *(uint4*)&Xs[xi[s] * XP + xc[s]] = f2tf4(xbuf[s]);
#pragma unroll
            for (int s = 0; s < 2; s++)
#pragma unroll
                for (int m = 0; m < 3; m++)
                    *(uint4*)&Ws[m][wr[s] * WP + wh[s]] = f2tf4(wbuf[m][s]);
            __syncthreads();
        }
    }

    float* G[3] = {g_k, g_q, g_v};
#pragma unroll
    for (int m = 0; m < 3; m++)
#pragma unroll
        for (int mt = 0; mt < 2; mt++) {
            int r0 = row0 + wm * 32 + mt * 16 + g;
#pragma unroll
            for (int nt = 0; nt < 4; nt++) {
                int c0 = wn * 32 + nt * 8 + 2 * t;
                float* dst = G[m] + (size_t)r0 * HH + c0;
                *(float2*)dst = make_float2(acc[m][mt][nt][0], acc[m][mt][nt][1]);
                *(float2*)(dst + (size_t)8 * HH) =
                    make_float2(acc[m][mt][nt][2], acc[m][mt][nt][3]);
            }
        }
}

// ---------------------------------------------------------------------------
// Kernel 2a: split-KV flash attention partials.
// Grid (NCHB, BB), block 128 = 4 warps. Each block: one chunk of <=8 KV
// tiles for one 64-row q-tile. fp16 m16n8k16, P in registers, double-
// buffered fp16 K/V (V transposed), ONE __syncthreads per tile.
// Writes unnormalized O + per-row (m, l) to scratch.
// ---------------------------------------------------------------------------
#define AP 36

__global__ __launch_bounds__(128, 3) void attn_part(void)
{
    __shared__ uint32_t Qh[64 * AP];
    __shared__ uint32_t Kb[2][64 * AP];
    __shared__ uint32_t Vb[2][64 * AP];

    const int tid  = threadIdx.x;
    const int lane = tid & 31;
    const int lw   = tid >> 5;
    const int g    = lane >> 2;
    const int t    = lane & 3;
    const int b    = blockIdx.y;

    // chunk id -> (qt, c), descending qt (big chunks scheduled first)
    int cid = blockIdx.x;
    int qt = 63, c = 0;
#pragma unroll 1
    for (int q = 63; q >= 0; q--) {
        int nch = (q + CH) >> 3;     // ceil((q+1)/8)
        if (cid < nch) { qt = q; c = cid; break; }
        cid -= nch;
    }
    const int kt0 = c * CH;
    const int kt1 = min(kt0 + CH, qt + 1);
    const int qrow0 = qt * 64;
    const float scale = 0.03125f;    // 1024^-0.5

    // Per-thread load slots: 8 float4 per 64x64 tile
    int li[8], lh[8];
#pragma unroll
    for (int s = 0; s < 8; s++) {
        int idx = tid + s * 128;
        li[s] = idx >> 4;
        lh[s] = (idx & 15) * 4;
    }

    // Stage Q (scaled -> fp16) and first K/V tile into buffer 0
#pragma unroll
    for (int s = 0; s < 8; s++) {
        float4 qv = *(const float4*)(g_q + ((size_t)b * TT + qrow0 + li[s]) * HH + lh[s]);
        qv.x *= scale; qv.y *= scale; qv.z *= scale; qv.w *= scale;
        *(uint2*)&Qh[li[s] * AP + lh[s] / 2] = f4toh2x2(qv);
    }
    {
        half* vh = (half*)Vb[0];
        const size_t rb = (size_t)b * TT + (size_t)kt0 * 64;
#pragma unroll
        for (int s = 0; s < 8; s++) {
            size_t go = (rb + li[s]) * HH + lh[s];
            *(uint2*)&Kb[0][li[s] * AP + lh[s] / 2] = f4toh2x2(*(const float4*)(g_k + go));
            float4 vv = *(const float4*)(g_v + go);
            int iw = li[s] >> 1, ib = li[s] & 1;
            vh[((lh[s] + 0) * AP + iw) * 2 + ib] = __float2half_rn(vv.x);
            vh[((lh[s] + 1) * AP + iw) * 2 + ib] = __float2half_rn(vv.y);
            vh[((lh[s] + 2) * AP + iw) * 2 + ib] = __float2half_rn(vv.z);
            vh[((lh[s] + 3) * AP + iw) * 2 + ib] = __float2half_rn(vv.w);
        }
    }
    __syncthreads();

    float m0v = -INFINITY, m1v = -INFINITY, l0 = 0.f, l1 = 0.f;
    float O[8][4];
#pragma unroll
    for (int nt = 0; nt < 8; nt++)
#pragma unroll
        for (int e = 0; e < 4; e++) O[nt][e] = 0.f;

    const int arow = lw * 16 + g;
    int pb = 0;

#pragma unroll 1
    for (int kt = kt0; kt < kt1; kt++) {
        const uint32_t* Kc = Kb[pb];
        const uint32_t* Vc = Vb[pb];

        // S = Qh * Kc^T
        float S[8][4];
#pragma unroll
        for (int nt = 0; nt < 8; nt++)
#pragma unroll
            for (int e = 0; e < 4; e++) S[nt][e] = 0.f;

#pragma unroll
        for (int kc = 0; kc < 4; kc++) {
            const int k0 = kc * 8;
            uint32_t a0 = Qh[arow * AP + k0 + t];
            uint32_t a1 = Qh[(arow + 8) * AP + k0 + t];
            uint32_t a2 = Qh[arow * AP + k0 + t + 4];
            uint32_t a3 = Qh[(arow + 8) * AP + k0 + t + 4];
#pragma unroll
            for (int nt = 0; nt < 8; nt++) {
                uint32_t b0 = Kc[(nt * 8 + g) * AP + k0 + t];
                uint32_t b1 = Kc[(nt * 8 + g) * AP + k0 + t + 4];
                mma16(S[nt], a0, a1, a2, a3, b0, b1);
            }
        }

        // Causal mask (diagonal tile only)
        if (kt == qt) {
            const int krow0 = kt * 64;
            int r0 = qrow0 + arow, r1 = r0 + 8;
#pragma unroll
            for (int nt = 0; nt < 8; nt++) {
                int cc = krow0 + nt * 8 + 2 * t;
                if (cc     > r0) S[nt][0] = -INFINITY;
                if (cc + 1 > r0) S[nt][1] = -INFINITY;
                if (cc     > r1) S[nt][2] = -INFINITY;
                if (cc + 1 > r1) S[nt][3] = -INFINITY;
            }
        }

        // Row max over lane quad
        float mt0 = -INFINITY, mt1 = -INFINITY;
#pragma unroll
        for (int nt = 0; nt < 8; nt++) {
            mt0 = fmaxf(mt0, fmaxf(S[nt][0], S[nt][1]));
            mt1 = fmaxf(mt1, fmaxf(S[nt][2], S[nt][3]));
        }
        mt0 = fmaxf(mt0, __shfl_xor_sync(0xffffffffu, mt0, 1));
        mt0 = fmaxf(mt0, __shfl_xor_sync(0xffffffffu, mt0, 2));
        mt1 = fmaxf(mt1, __shfl_xor_sync(0xffffffffu, mt1, 1));
        mt1 = fmaxf(mt1, __shfl_xor_sync(0xffffffffu, mt1, 2));

        float mn0 = fmaxf(m0v, mt0), mn1 = fmaxf(m1v, mt1);
        float cr0 = __expf(m0v - mn0), cr1 = __expf(m1v - mn1);

        // P = exp(S - mn): pack straight into fp16 A-fragments
        uint32_t pl[8], ph[8];
        float rs0 = 0.f, rs1 = 0.f;
#pragma unroll
        for (int nt = 0; nt < 8; nt++) {
            float p0 = __expf(S[nt][0] - mn0);
            float p1 = __expf(S[nt][1] - mn0);
            float p2 = __expf(S[nt][2] - mn1);
            float p3 = __expf(S[nt][3] - mn1);
            rs0 += p0 + p1;
            rs1 += p2 + p3;
            pl[nt] = packh2(p0, p1);
            ph[nt] = packh2(p2, p3);
        }
        rs0 += __shfl_xor_sync(0xffffffffu, rs0, 1);
        rs0 += __shfl_xor_sync(0xffffffffu, rs0, 2);
        rs1 += __shfl_xor_sync(0xffffffffu, rs1, 1);
        rs1 += __shfl_xor_sync(0xffffffffu, rs1, 2);

        l0 = l0 * cr0 + rs0;
        l1 = l1 * cr1 + rs1;
        m0v = mn0; m1v = mn1;
#pragma unroll
        for (int nt = 0; nt < 8; nt++) {
            O[nt][0] *= cr0; O[nt][1] *= cr0;
            O[nt][2] *= cr1; O[nt][3] *= cr1;
        }

        // Stage next tile into alternate buffers (inline LDG->cvt->STS;
        // other warps/blocks hide the load latency)
        if (kt + 1 < kt1) {
            uint32_t* Kn = Kb[1 - pb];
            half*     Vn = (half*)Vb[1 - pb];
            const size_t rb = (size_t)b * TT + (size_t)(kt + 1) * 64;
#pragma unroll
            for (int s = 0; s < 8; s++) {
                size_t go = (rb + li[s]) * HH + lh[s];
                *(uint2*)&Kn[li[s] * AP + lh[s] / 2] = f4toh2x2(*(const float4*)(g_k + go));
                float4 vv = *(const float4*)(g_v + go);
                int iw = li[s] >> 1, ib = li[s] & 1;
                Vn[((lh[s] + 0) * AP + iw) * 2 + ib] = __float2half_rn(vv.x);
                Vn[((lh[s] + 1) * AP + iw) * 2 + ib] = __float2half_rn(vv.y);
                Vn[((lh[s] + 2) * AP + iw) * 2 + ib] = __float2half_rn(vv.z);
                Vn[((lh[s] + 3) * AP + iw) * 2 + ib] = __float2half_rn(vv.w);
            }
        }

        // O += P * V
#pragma unroll
        for (int kc = 0; kc < 4; kc++) {
            uint32_t a0 = pl[2 * kc], a1 = ph[2 * kc];
            uint32_t a2 = pl[2 * kc + 1], a3 = ph[2 * kc + 1];
            const int k0 = kc * 8;
#pragma unroll
            for (int nt = 0; nt < 8; nt++) {
                uint32_t b0 = Vc[(nt * 8 + g) * AP + k0 + t];
                uint32_t b1 = Vc[(nt * 8 + g) * AP + k0 + t + 4];
                mma16(O[nt], a0, a1, a2, a3, b0, b1);
            }
        }
        __syncthreads();
        pb ^= 1;
    }

    // Write partials: unnormalized O, per-row m and l
    const size_t pbase = ((size_t)(b * NQT + qt) * MAXC + c) * 64;
#pragma unroll
    for (int nt = 0; nt < 8; nt++) {
        size_t o0 = (pbase + arow) * 64 + nt * 8 + 2 * t;
        *(float2*)(g_Opart + o0)            = make_float2(O[nt][0], O[nt][1]);
        *(float2*)(g_Opart + o0 + 8 * 64)   = make_float2(O[nt][2], O[nt][3]);
    }
    if (t == 0) {
        g_mpart[pbase + arow]     = m0v;
        g_lpart[pbase + arow]     = l0;
        g_mpart[pbase + arow + 8] = m1v;
        g_lpart[pbase + arow + 8] = l1;
    }
}

// ---------------------------------------------------------------------------
// Kernel 2b: merge partials.  Grid (NQT, BB), 256 thr.
// thread = (row = tid/4, 16-col group = tid%4).
// ---------------------------------------------------------------------------
__global__ __launch_bounds__(256) void attn_merge(float* __restrict__ out)
{
    const int qt  = blockIdx.x;
    const int b   = blockIdx.y;
    const int tid = threadIdx.x;
    const int row = tid >> 2;
    const int cg  = (tid & 3) * 16;
    const int nc  = (qt + CH) >> 3;          // ceil((qt+1)/8)

    const size_t pbase = (size_t)(b * NQT + qt) * MAXC;

    float mv[MAXC], lv[MAXC];
    float M = -INFINITY;
#pragma unroll 1
    for (int c = 0; c < nc; c++) {
        mv[c] = g_mpart[(pbase + c) * 64 + row];
        lv[c] = g_lpart[(pbase + c) * 64 + row];
        M = fmaxf(M, mv[c]);
    }
    float L = 0.f;
    float w[MAXC];
#pragma unroll 1
    for (int c = 0; c < nc; c++) {
        w[c] = __expf(mv[c] - M);
        L += w[c] * lv[c];
    }
    const float invL = 1.0f / L;

    float acc[16];
#pragma unroll
    for (int i = 0; i < 16; i++) acc[i] = 0.f;

#pragma unroll 1
    for (int c = 0; c < nc; c++) {
        const float* op = g_Opart + ((pbase + c) * 64 + row) * 64 + cg;
        const float wc = w[c];
#pragma unroll
        for (int i = 0; i < 4; i++) {
            float4 v = *(const float4*)(op + i * 4);
            acc[i * 4 + 0] += wc * v.x;
            acc[i * 4 + 1] += wc * v.y;
            acc[i * 4 + 2] += wc * v.z;
            acc[i * 4 + 3] += wc * v.w;
        }
    }

    float* dst = out + ((size_t)b * TT + qt * 64 + row) * HH + cg;
#pragma unroll
    for (int i = 0; i < 4; i++) {
        *(float4*)(dst + i * 4) = make_float4(acc[i * 4 + 0] * invL,
                                              acc[i * 4 + 1] * invL,
                                              acc[i * 4 + 2] * invL,
                                              acc[i * 4 + 3] * invL);
    }
}

// ---------------------------------------------------------------------------
extern "C" void kernel_launch(void* const* d_in, const int* in_sizes, int n_in,
                              void* d_out, int out_size)
{
    const float* x  = (const float*)d_in[0];
    const float* Wk = (const float*)d_in[1];
    const float* Wq = (const float*)d_in[2];
    const float* Wv = (const float*)d_in[3];
    float* out = (float*)d_out;

    proj_kernel<<<(BB * TT) / PM, 256>>>(x, Wk, Wq, Wv);
    attn_part<<<dim3(NCHB, BB), 128>>>();
    attn_merge<<<dim3(NQT, BB), 256>>>(out);
}